// round 4
// baseline (speedup 1.0000x reference)
#include <cuda_runtime.h>
#include <cstdint>
#include <cstddef>

#define NS 512
#define NB 1024
#define NT 64
#define PAIRS_PER_BLOCK 4
#define THREADS_PER_BLOCK (PAIRS_PER_BLOCK * 64)   // 256
#define GRID_BLOCKS (NB / PAIRS_PER_BLOCK)         // 256

__device__ float g_partial[NB];
__device__ unsigned int g_ctr = 0;

typedef unsigned long long u64;

// ---------- packed f32x2 helpers (sm_100+) ----------
__device__ __forceinline__ u64 pack2(float lo, float hi) {
    u64 r; asm("mov.b64 %0, {%1, %2};" : "=l"(r) : "f"(lo), "f"(hi)); return r;
}
__device__ __forceinline__ void unpack2(u64 v, float& lo, float& hi) {
    asm("mov.b64 {%0, %1}, %2;" : "=f"(lo), "=f"(hi) : "l"(v));
}
__device__ __forceinline__ void fma2(u64& acc, u64 a, u64 b) {
    asm("fma.rn.f32x2 %0, %1, %2, %0;" : "+l"(acc) : "l"(a), "l"(b));
}
__device__ __forceinline__ u64 add2(u64 a, u64 b) {
    u64 r; asm("add.rn.f32x2 %0, %1, %2;" : "=l"(r) : "l"(a), "l"(b)); return r;
}
__device__ __forceinline__ u64 mul2(u64 a, u64 b) {
    u64 r; asm("mul.rn.f32x2 %0, %1, %2;" : "=l"(r) : "l"(a), "l"(b)); return r;
}
__device__ __forceinline__ float frcp(float x) {
    float r; asm("rcp.approx.f32 %0, %1;" : "=f"(r) : "f"(x)); return r;
}
__device__ __forceinline__ void sts128(u64* p, float a, float b, float c, float d) {
    asm volatile("st.shared.v4.f32 [%0], {%1, %2, %3, %4};"
                 :: "l"(p), "f"(a), "f"(b), "f"(c), "f"(d) : "memory");
}
#define BAR_ARRIVE(id) asm volatile("bar.arrive %0, 64;" :: "r"(id) : "memory")
#define BAR_SYNC(id)   asm volatile("bar.sync %0, 64;"   :: "r"(id) : "memory")

__global__ void __launch_bounds__(THREADS_PER_BLOCK, 2)
crf_kernel(const float* __restrict__ em,
           const float* __restrict__ trans,
           const float* __restrict__ start_t,
           const float* __restrict__ end_t,
           const int* __restrict__ tags,
           const int* __restrict__ mask,
           float* __restrict__ out) {
    // q buffers: duplicated pairs, double-buffered. partial buffers: double-buffered.
    __shared__ __align__(16) u64 qbuf[PAIRS_PER_BLOCK][2][NT];
    __shared__ __align__(16) u64 pbuf[PAIRS_PER_BLOCK][2][32];
    __shared__ float red_smem[8];
    __shared__ int is_last;

    const int tid  = threadIdx.x;
    const int wid  = tid >> 5;
    const int lane = tid & 31;
    const int pair = wid >> 1;       // 0..3
    const int role = wid & 1;        // 0 = rows 0..31 producer, 1 = rows 32..63 + finalize
    const int b    = blockIdx.x * PAIRS_PER_BLOCK + pair;
    const int c0   = lane * 2;       // my two tag columns
    const int idA  = 1 + 2 * pair;   // partial-ready barrier
    const int idB  = 2 + 2 * pair;   // q-ready barrier

    const size_t SSTR = (size_t)NB * NT;
    const float* emb = em + (size_t)b * NT + c0;

    float sc = 0.f, Mtot = 0.f;
    float qx = 0.f, qy = 0.f;

    // ---------------- numerator (role 1 only), before E regs go live ----------------
    if (role == 1) {
        int msum = 0;
#pragma unroll
        for (int k = 0; k < 16; k++) {
            int s = 1 + lane + (k << 5);
            if (s < NS) {
                int tp = tags[(s - 1) * NB + b];
                int tc = tags[s * NB + b];
                int mv = mask[s * NB + b];
                float term = trans[tp * NT + tc] + em[((size_t)s * NB + b) * NT + tc];
                sc += term * (float)mv;
                msum += mv;
            }
        }
#pragma unroll
        for (int off = 16; off; off >>= 1) {
            sc   += __shfl_xor_sync(0xffffffffu, sc, off);
            msum += __shfl_xor_sync(0xffffffffu, msum, off);
        }
        int t0 = tags[b];
        sc += start_t[t0] + em[(size_t)b * NT + t0];
        int seq_end = mask[b] + msum - 1;
        int lt = tags[(size_t)seq_end * NB + b];
        sc += end_t[lt];

        // q0 and its duplicated store (read buffer parity for s=1 is 1)
        float2 e0 = *reinterpret_cast<const float2*>(emb);
        float2 st = *reinterpret_cast<const float2*>(start_t + c0);
        qx = __expf(st.x + e0.x);
        qy = __expf(st.y + e0.y);
        sts128(&qbuf[pair][1][c0], qx, qx, qy, qy);
    }

    // ---------------- E = exp(transitions), my 32 rows, columns (c0,c0+1) ----------------
    u64 Ecol[32];
    const int rbase = role << 5;
#pragma unroll
    for (int i = 0; i < 32; i++) {
        float2 tr = *reinterpret_cast<const float2*>(trans + (rbase + i) * NT + c0);
        Ecol[i] = pack2(__expf(tr.x), __expf(tr.y));
    }

    __syncthreads();

    if (role == 0) {
        // ======== producer: partial matvec over rows 0..31 ========
        for (int k = 0; k < 128; k++) {
            int sb = 1 + (k << 2);
#pragma unroll
            for (int u = 0; u < 4; u++) {
                int s = sb + u;
                if (s < NS) {
                    int r = s & 1;
                    const u64* q = qbuf[pair][r];
                    u64 A0 = 0, A1 = 0, A2 = 0, A3 = 0;
#pragma unroll
                    for (int i = 0; i < 32; i += 4) {
                        ulonglong2 pA = *reinterpret_cast<const ulonglong2*>(q + i);
                        ulonglong2 pB = *reinterpret_cast<const ulonglong2*>(q + i + 2);
                        fma2(A0, pA.x, Ecol[i]);     fma2(A1, pA.y, Ecol[i + 1]);
                        fma2(A2, pB.x, Ecol[i + 2]); fma2(A3, pB.y, Ecol[i + 3]);
                    }
                    pbuf[pair][r][lane] = add2(add2(A0, A1), add2(A2, A3));
                    BAR_ARRIVE(idA);            // partial(r) ready
                    BAR_SYNC(idB);              // wait q(r^1) for next step
                }
            }
        }
    } else {
        // ======== consumer: rows 32..63, combine + finalize ========
        float2 pf0 = *reinterpret_cast<const float2*>(emb + 1 * SSTR);
        float2 pf1 = *reinterpret_cast<const float2*>(emb + 2 * SSTR);
        float2 pf2 = *reinterpret_cast<const float2*>(emb + 3 * SSTR);
        float2 pf3 = *reinterpret_cast<const float2*>(emb + 4 * SSTR);
        u64 eemCur = pack2(__expf(pf0.x), __expf(pf0.y));
        int mkA = mask[1 * NB + b];
        int mkB = mask[2 * NB + b];

#define CRF_STEP(S, PF_USE, PF_WR, MK_SLOT)                                        \
    do {                                                                           \
        if ((S) < NS) {                                                            \
            const int r = (S) & 1;                                                 \
            int mk = MK_SLOT;                                                      \
            __syncwarp();                                                          \
            const u64* q = qbuf[pair][r];                                          \
            u64 A0 = 0, A1 = 0, A2 = 0, A3 = 0;                                    \
            _Pragma("unroll")                                                      \
            for (int i = 32; i < 64; i += 4) {                                     \
                ulonglong2 pA = *reinterpret_cast<const ulonglong2*>(q + i);       \
                ulonglong2 pB = *reinterpret_cast<const ulonglong2*>(q + i + 2);   \
                fma2(A0, pA.x, Ecol[i - 32]); fma2(A1, pA.y, Ecol[i - 31]);        \
                fma2(A2, pB.x, Ecol[i - 30]); fma2(A3, pB.y, Ecol[i - 29]);        \
            }                                                                      \
            u64 accT = add2(add2(A0, A1), add2(A2, A3));                           \
            BAR_SYNC(idA);                                                         \
            accT = add2(accT, pbuf[pair][r][lane]);                                \
            float ax, ay; unpack2(accT, ax, ay);                                   \
            float a0 = __shfl_sync(0xffffffffu, ax, 0);                            \
            float r0 = frcp(a0);                                                   \
            u64 q2 = mul2(mul2(accT, pack2(r0, r0)), eemCur);                      \
            float nqx, nqy; unpack2(q2, nqx, nqy);                                 \
            float lr = __logf(a0);                                                 \
            if (mk) { qx = nqx; qy = nqy; Mtot += lr; }                            \
            sts128(&qbuf[pair][r ^ 1][c0], qx, qx, qy, qy);                        \
            BAR_ARRIVE(idB);                                                       \
            eemCur = pack2(__expf(PF_USE.x), __expf(PF_USE.y));                    \
            if ((S) + 4 < NS)                                                      \
                PF_WR = *reinterpret_cast<const float2*>(emb + (size_t)((S) + 4) * SSTR); \
            if ((S) + 2 < NS)                                                      \
                MK_SLOT = mask[((S) + 2) * NB + b];                                \
        }                                                                          \
    } while (0)

        for (int k = 0; k < 128; k++) {
            int sb = 1 + (k << 2);
            CRF_STEP(sb,     pf1, pf0, mkA);
            CRF_STEP(sb + 1, pf2, pf1, mkB);
            CRF_STEP(sb + 2, pf3, pf2, mkA);
            CRF_STEP(sb + 3, pf0, pf3, mkB);
        }
#undef CRF_STEP

        // normalizer = Mtot + log( sum_j q_j * exp(end_j) )
        float2 et = *reinterpret_cast<const float2*>(end_t + c0);
        float v = qx * __expf(et.x) + qy * __expf(et.y);
#pragma unroll
        for (int off = 16; off; off >>= 1)
            v += __shfl_xor_sync(0xffffffffu, v, off);
        if (lane == 0) {
            g_partial[b] = sc - (Mtot + __logf(v));
            __threadfence();
        }
    }

    // ---------------- merged deterministic final reduction ----------------
    __syncthreads();
    if (tid == 0) {
        unsigned int old = atomicAdd(&g_ctr, 1);
        is_last = (old == (unsigned int)(gridDim.x - 1));
    }
    __syncthreads();
    if (is_last) {
        __threadfence();
        float s = 0.f;
        for (int i = tid; i < NB; i += THREADS_PER_BLOCK)
            s += g_partial[i];
#pragma unroll
        for (int off = 16; off; off >>= 1)
            s += __shfl_xor_sync(0xffffffffu, s, off);
        if ((tid & 31) == 0) red_smem[tid >> 5] = s;
        __syncthreads();
        if (tid < 32) {
            s = (tid < 8) ? red_smem[tid] : 0.f;
#pragma unroll
            for (int off = 4; off; off >>= 1)
                s += __shfl_xor_sync(0xffffffffu, s, off);
            if (tid == 0) { out[0] = s; g_ctr = 0; }
        }
    }
}

extern "C" void kernel_launch(void* const* d_in, const int* in_sizes, int n_in,
                              void* d_out, int out_size) {
    const float* em    = (const float*)d_in[0];
    const float* trans = (const float*)d_in[1];
    const float* st    = (const float*)d_in[2];
    const float* et    = (const float*)d_in[3];
    const int*   tags  = (const int*)d_in[4];
    const int*   mask  = (const int*)d_in[5];

    crf_kernel<<<GRID_BLOCKS, THREADS_PER_BLOCK>>>(em, trans, st, et, tags, mask,
                                                   (float*)d_out);
}